// round 1
// baseline (speedup 1.0000x reference)
#include <cuda_runtime.h>
#include <cuda_bf16.h>
#include <math.h>

// Problem constants
#define BATCH 2
#define SEQ   2048
#define DMODEL 1024
#define NHEAD 16
#define DK    64
#define MROWS (BATCH * SEQ)   // 4096

// ---------------- scratch (no cudaMalloc allowed) ----------------
__device__ float g_q[BATCH * NHEAD * SEQ * DK];      // [B,H,S,DK]
__device__ float g_k[BATCH * NHEAD * SEQ * DK];
__device__ float g_v[BATCH * NHEAD * SEQ * DK];
__device__ float g_attn[MROWS * DMODEL];             // [B,S,D]

// ================= SGEMM: C = A(MxK) * W(NxK)^T + bias =================
// Tiles: 128x128x16, 256 threads, 8x8 per-thread register tile.
// headLayout=1 -> write out[((b*H+h)*S+s)*DK + d] instead of row-major.
#define BM 128
#define BN 128
#define BK 16

__global__ __launch_bounds__(256) void sgemm_nt(
    const float* __restrict__ A, const float* __restrict__ W,
    const float* __restrict__ bias, float* __restrict__ C,
    int M, int N, int K, int headLayout)
{
    __shared__ float As[BK][BM];
    __shared__ float Bs[BK][BN];

    const int tid = threadIdx.x;
    const int bm = blockIdx.y * BM;
    const int bn = blockIdx.x * BN;

    // loader indices: each thread loads 2 float4 from A and 2 from W per k-tile
    const int lr = tid >> 2;          // 0..63
    const int lc = (tid & 3) * 4;     // 0,4,8,12

    const int tx = tid & 15;          // col group
    const int ty = tid >> 4;          // row group

    float acc[8][8];
#pragma unroll
    for (int i = 0; i < 8; i++)
#pragma unroll
        for (int j = 0; j < 8; j++) acc[i][j] = 0.0f;

    for (int k0 = 0; k0 < K; k0 += BK) {
        // load A tile (transposed into As[k][m])
        {
            const float* p = A + (size_t)(bm + lr) * K + k0 + lc;
            float4 a0 = *(const float4*)p;
            float4 a1 = *(const float4*)(p + (size_t)64 * K);
            As[lc + 0][lr] = a0.x; As[lc + 1][lr] = a0.y;
            As[lc + 2][lr] = a0.z; As[lc + 3][lr] = a0.w;
            As[lc + 0][lr + 64] = a1.x; As[lc + 1][lr + 64] = a1.y;
            As[lc + 2][lr + 64] = a1.z; As[lc + 3][lr + 64] = a1.w;
        }
        // load W tile (transposed into Bs[k][n])
        {
            const float* p = W + (size_t)(bn + lr) * K + k0 + lc;
            float4 b0 = *(const float4*)p;
            float4 b1 = *(const float4*)(p + (size_t)64 * K);
            Bs[lc + 0][lr] = b0.x; Bs[lc + 1][lr] = b0.y;
            Bs[lc + 2][lr] = b0.z; Bs[lc + 3][lr] = b0.w;
            Bs[lc + 0][lr + 64] = b1.x; Bs[lc + 1][lr + 64] = b1.y;
            Bs[lc + 2][lr + 64] = b1.z; Bs[lc + 3][lr + 64] = b1.w;
        }
        __syncthreads();

#pragma unroll
        for (int k = 0; k < BK; k++) {
            float a[8], b[8];
            float4 a0 = *(const float4*)&As[k][ty * 8];
            float4 a1 = *(const float4*)&As[k][ty * 8 + 4];
            float4 b0 = *(const float4*)&Bs[k][tx * 8];
            float4 b1 = *(const float4*)&Bs[k][tx * 8 + 4];
            a[0]=a0.x; a[1]=a0.y; a[2]=a0.z; a[3]=a0.w;
            a[4]=a1.x; a[5]=a1.y; a[6]=a1.z; a[7]=a1.w;
            b[0]=b0.x; b[1]=b0.y; b[2]=b0.z; b[3]=b0.w;
            b[4]=b1.x; b[5]=b1.y; b[6]=b1.z; b[7]=b1.w;
#pragma unroll
            for (int i = 0; i < 8; i++)
#pragma unroll
                for (int j = 0; j < 8; j++)
                    acc[i][j] = fmaf(a[i], b[j], acc[i][j]);
        }
        __syncthreads();
    }

    // epilogue
#pragma unroll
    for (int i = 0; i < 8; i++) {
        const int gm = bm + ty * 8 + i;
#pragma unroll
        for (int j = 0; j < 8; j++) {
            const int gn = bn + tx * 8 + j;
            const float val = acc[i][j] + bias[gn];
            if (headLayout) {
                const int b = gm / SEQ, s = gm % SEQ;
                const int h = gn / DK, d = gn % DK;
                C[(((size_t)(b * NHEAD + h) * SEQ) + s) * DK + d] = val;
            } else {
                C[(size_t)gm * N + gn] = val;
            }
        }
    }
}

// ================= Flash attention (fp32) =================
// grid: (SEQ/64, B*H), block 256. Per CTA: 64 q-rows, loop 64-key tiles.
// Thread (ty=tid>>4, tx=tid&15): 4x4 tile. Rows ty*4..+4 stay fixed across
// both phases so the online-softmax state lives in registers.
__global__ __launch_bounds__(256) void attn_kernel(
    const float* __restrict__ Qg, const float* __restrict__ Kg,
    const float* __restrict__ Vg, float* __restrict__ Og)
{
    __shared__ float Qs[DK][64];   // Qs[d][r]
    __shared__ float KV[64][64];   // K phase: KV[d][c]; V phase: KV[j][d]
    __shared__ float Ps[64][64];   // Ps[r][j]

    const int tid = threadIdx.x;
    const int bh = blockIdx.y;
    const int q0 = blockIdx.x * 64;

    const float* Qb = Qg + ((size_t)bh * SEQ + q0) * DK;
    const float* Kb = Kg + (size_t)bh * SEQ * DK;
    const float* Vb = Vg + (size_t)bh * SEQ * DK;

    // load Q tile transposed
    {
        const int r = tid >> 2;
        const int c0 = (tid & 3) * 16;
        const float* p = Qb + r * DK + c0;
#pragma unroll
        for (int i = 0; i < 16; i += 4) {
            float4 v = *(const float4*)(p + i);
            Qs[c0 + i + 0][r] = v.x; Qs[c0 + i + 1][r] = v.y;
            Qs[c0 + i + 2][r] = v.z; Qs[c0 + i + 3][r] = v.w;
        }
    }

    const int tx = tid & 15;
    const int ty = tid >> 4;

    float m_i[4], l_i[4], acc[4][4];
#pragma unroll
    for (int i = 0; i < 4; i++) {
        m_i[i] = -1e30f; l_i[i] = 0.0f;
#pragma unroll
        for (int j = 0; j < 4; j++) acc[i][j] = 0.0f;
    }

    for (int kt = 0; kt < SEQ; kt += 64) {
        __syncthreads();   // prior PV reads of KV/Ps done (and Qs ready, iter 0)
        // load K tile transposed: KV[d][c]
        {
            const int c = tid >> 2;
            const int d0 = (tid & 3) * 16;
            const float* p = Kb + (size_t)(kt + c) * DK + d0;
#pragma unroll
            for (int i = 0; i < 16; i += 4) {
                float4 v = *(const float4*)(p + i);
                KV[d0 + i + 0][c] = v.x; KV[d0 + i + 1][c] = v.y;
                KV[d0 + i + 2][c] = v.z; KV[d0 + i + 3][c] = v.w;
            }
        }
        __syncthreads();

        // phase A: scores 4x4
        float s[4][4];
#pragma unroll
        for (int i = 0; i < 4; i++)
#pragma unroll
            for (int j = 0; j < 4; j++) s[i][j] = 0.0f;

#pragma unroll 8
        for (int d = 0; d < DK; d++) {
            float4 qv = *(const float4*)&Qs[d][ty * 4];
            float4 kv = *(const float4*)&KV[d][tx * 4];
            float q[4] = {qv.x, qv.y, qv.z, qv.w};
            float k[4] = {kv.x, kv.y, kv.z, kv.w};
#pragma unroll
            for (int i = 0; i < 4; i++)
#pragma unroll
                for (int j = 0; j < 4; j++)
                    s[i][j] = fmaf(q[i], k[j], s[i][j]);
        }

        // online softmax (rows replicated across the 16 lanes sharing ty)
        float fac[4];
#pragma unroll
        for (int i = 0; i < 4; i++) {
            float mx = fmaxf(fmaxf(s[i][0], s[i][1]), fmaxf(s[i][2], s[i][3])) * 0.125f;
            mx = fmaxf(mx, __shfl_xor_sync(0xffffffffu, mx, 1));
            mx = fmaxf(mx, __shfl_xor_sync(0xffffffffu, mx, 2));
            mx = fmaxf(mx, __shfl_xor_sync(0xffffffffu, mx, 4));
            mx = fmaxf(mx, __shfl_xor_sync(0xffffffffu, mx, 8));
            const float mn = fmaxf(m_i[i], mx);
            fac[i] = __expf(m_i[i] - mn);
            m_i[i] = mn;
            float ls = 0.0f;
#pragma unroll
            for (int j = 0; j < 4; j++) {
                const float p = __expf(fmaf(s[i][j], 0.125f, -mn));
                s[i][j] = p;
                ls += p;
            }
            ls += __shfl_xor_sync(0xffffffffu, ls, 1);
            ls += __shfl_xor_sync(0xffffffffu, ls, 2);
            ls += __shfl_xor_sync(0xffffffffu, ls, 4);
            ls += __shfl_xor_sync(0xffffffffu, ls, 8);
            l_i[i] = l_i[i] * fac[i] + ls;
        }

        __syncthreads();   // all reads of KV (K) done

        // store P, load V into KV (natural layout KV[j][d])
#pragma unroll
        for (int i = 0; i < 4; i++)
#pragma unroll
            for (int j = 0; j < 4; j++)
                Ps[ty * 4 + i][tx * 4 + j] = s[i][j];
        {
            const int j = tid >> 2;
            const int d0 = (tid & 3) * 16;
            const float* p = Vb + (size_t)(kt + j) * DK + d0;
#pragma unroll
            for (int i = 0; i < 16; i += 4)
                *(float4*)&KV[j][d0 + i] = *(const float4*)(p + i);
        }
        __syncthreads();

        // phase B: O += P * V   (dims tx*4..+4, rows ty*4..+4)
#pragma unroll
        for (int i = 0; i < 4; i++)
#pragma unroll
            for (int j = 0; j < 4; j++) acc[i][j] *= fac[i];

#pragma unroll 8
        for (int j = 0; j < 64; j++) {
            float4 vv = *(const float4*)&KV[j][tx * 4];
            float v[4] = {vv.x, vv.y, vv.z, vv.w};
            float p[4];
#pragma unroll
            for (int i = 0; i < 4; i++) p[i] = Ps[ty * 4 + i][j];
#pragma unroll
            for (int i = 0; i < 4; i++)
#pragma unroll
                for (int d = 0; d < 4; d++)
                    acc[i][d] = fmaf(p[i], v[d], acc[i][d]);
        }
    }

    // epilogue: normalize and write to [B,S,D] scratch (heads re-interleaved)
    const int b = bh >> 4;   // / NHEAD
    const int h = bh & 15;
#pragma unroll
    for (int i = 0; i < 4; i++) {
        const float inv = 1.0f / l_i[i];
        const int r = q0 + ty * 4 + i;
        float4 o;
        o.x = acc[i][0] * inv; o.y = acc[i][1] * inv;
        o.z = acc[i][2] * inv; o.w = acc[i][3] * inv;
        float* op = Og + ((size_t)b * SEQ + r) * DMODEL + h * DK + tx * 4;
        *(float4*)op = o;
    }
}

// ================= launch =================
extern "C" void kernel_launch(void* const* d_in, const int* in_sizes, int n_in,
                              void* d_out, int out_size)
{
    const float* x  = (const float*)d_in[0];
    const float* Wq = (const float*)d_in[1];
    const float* bq = (const float*)d_in[2];
    const float* Wk = (const float*)d_in[3];
    const float* bk = (const float*)d_in[4];
    const float* Wv = (const float*)d_in[5];
    const float* bv = (const float*)d_in[6];
    const float* Wo = (const float*)d_in[7];
    const float* bo = (const float*)d_in[8];
    float* out = (float*)d_out;

    float *gq, *gk, *gv, *ga;
    cudaGetSymbolAddress((void**)&gq, g_q);
    cudaGetSymbolAddress((void**)&gk, g_k);
    cudaGetSymbolAddress((void**)&gv, g_v);
    cudaGetSymbolAddress((void**)&ga, g_attn);

    dim3 blk(256);
    dim3 gp(DMODEL / BN, MROWS / BM);   // (8, 32)

    sgemm_nt<<<gp, blk>>>(x, Wq, bq, gq, MROWS, DMODEL, DMODEL, 1);
    sgemm_nt<<<gp, blk>>>(x, Wk, bk, gk, MROWS, DMODEL, DMODEL, 1);
    sgemm_nt<<<gp, blk>>>(x, Wv, bv, gv, MROWS, DMODEL, DMODEL, 1);

    attn_kernel<<<dim3(SEQ / 64, BATCH * NHEAD), blk>>>(gq, gk, gv, ga);

    sgemm_nt<<<gp, blk>>>(ga, Wo, bo, out, MROWS, DMODEL, DMODEL, 0);
}